// round 1
// baseline (speedup 1.0000x reference)
#include <cuda_runtime.h>
#include <cstddef>

// Problem constants
#define BB  4
#define SSQ 2048
#define DDm 1024
#define HHn 16
#define DHH 64
#define FFd 4096
#define BSr (BB*SSQ)      // 8192 rows
#define EPSLN 1e-5f

// ---------------- scratch (device globals; allocation-free) ----------------
__device__ float g_q  [BSr*DDm];
__device__ float g_k  [BSr*DDm];
__device__ float g_v  [BSr*DDm];
__device__ float g_ctx[BSr*DDm];
__device__ float g_y1 [BSr*DDm];
__device__ float g_x  [BSr*DDm];
__device__ float g_h  [(size_t)BSr*FFd];
__device__ float g_y2 [BSr*DDm];

// ---------------- generic SGEMM: C[M,N] = A[M,K] @ B + bias (+res)(relu) ----
// QKV==1: B laid out as [H, K, DH] (head-stacked), logical col n -> (h=n>>6, e=n&63)
// QKV==0: B row-major [K, N]
template<int QKV, int RELU, int RES>
__global__ __launch_bounds__(256)
void gemm_k(const float* __restrict__ A, const float* __restrict__ B,
            const float* __restrict__ bias, const float* __restrict__ res,
            float* __restrict__ C, int M, int N, int K)
{
    __shared__ float As[8][128];
    __shared__ float Bs[8][128];

    const int tid = threadIdx.x;
    const int bm = blockIdx.y * 128;
    const int bn = blockIdx.x * 128;

    const int arow = tid >> 1;            // 0..127
    const int acol = (tid & 1) * 4;       // 0 or 4
    const int brow = tid >> 5;            // 0..7
    const int bcol = (tid & 31) * 4;      // 0..124

    const int tx = tid & 15;              // col group
    const int ty = tid >> 4;              // row group

    float acc[8][8];
#pragma unroll
    for (int i = 0; i < 8; i++)
#pragma unroll
        for (int j = 0; j < 8; j++) acc[i][j] = 0.0f;

    const float* Aptr = A + (size_t)(bm + arow) * K + acol;

    for (int k0 = 0; k0 < K; k0 += 8) {
        float4 av = *(const float4*)(Aptr + k0);
        As[acol + 0][arow] = av.x;
        As[acol + 1][arow] = av.y;
        As[acol + 2][arow] = av.z;
        As[acol + 3][arow] = av.w;

        float4 bv;
        if (QKV) {
            int n = bn + bcol;
            bv = *(const float4*)(B + (size_t)(n >> 6) * (DDm * DHH)
                                    + (size_t)(k0 + brow) * DHH + (n & 63));
        } else {
            bv = *(const float4*)(B + (size_t)(k0 + brow) * N + bn + bcol);
        }
        *(float4*)&Bs[brow][bcol] = bv;

        __syncthreads();

#pragma unroll
        for (int kk = 0; kk < 8; kk++) {
            float a[8], bb[8];
            *(float4*)(a)      = *(float4*)&As[kk][ty * 8];
            *(float4*)(a + 4)  = *(float4*)&As[kk][ty * 8 + 4];
            *(float4*)(bb)     = *(float4*)&Bs[kk][tx * 8];
            *(float4*)(bb + 4) = *(float4*)&Bs[kk][tx * 8 + 4];
#pragma unroll
            for (int i = 0; i < 8; i++)
#pragma unroll
                for (int j = 0; j < 8; j++)
                    acc[i][j] += a[i] * bb[j];
        }
        __syncthreads();
    }

    // epilogue
#pragma unroll
    for (int i = 0; i < 8; i++) {
        int r = bm + ty * 8 + i;
#pragma unroll
        for (int j = 0; j < 8; j += 4) {
            int c = bn + tx * 8 + j;
            float4 v;
            v.x = acc[i][j + 0] + bias[c + 0];
            v.y = acc[i][j + 1] + bias[c + 1];
            v.z = acc[i][j + 2] + bias[c + 2];
            v.w = acc[i][j + 3] + bias[c + 3];
            if (RES) {
                float4 rv = *(const float4*)&res[(size_t)r * N + c];
                v.x += rv.x; v.y += rv.y; v.z += rv.z; v.w += rv.w;
            }
            if (RELU) {
                v.x = fmaxf(v.x, 0.0f); v.y = fmaxf(v.y, 0.0f);
                v.z = fmaxf(v.z, 0.0f); v.w = fmaxf(v.w, 0.0f);
            }
            *(float4*)&C[(size_t)r * N + c] = v;
        }
    }
}

// ---------------- flash attention (fp32), 64x64 tiles, online softmax -------
// Q,K,V,CTX all in [B, S, H*DH] layout. Per-(b,h) slice: row stride = D.
#define ATP 68   // padded row (floats), 16B-aligned rows
__global__ __launch_bounds__(256)
void attn_k(const float* __restrict__ Q, const float* __restrict__ Kg,
            const float* __restrict__ Vg, float* __restrict__ CTX)
{
    extern __shared__ float sm[];
    float* sQt = sm;                    // [64][ATP] : [e][r]
    float* sKt = sm + 64 * ATP;         // [64][ATP] : [e][c]
    float* sV  = sm + 2 * 64 * ATP;     // [64][64]  : [kk][e]
    float* sPt = sm + 2 * 64 * ATP + 64 * 64;  // [64][ATP] : [kk][r]

    const int b = blockIdx.z, h = blockIdx.y;
    const int q0 = blockIdx.x * 64;
    const int tid = threadIdx.x;
    const int tx = tid & 15, ty = tid >> 4;

    // load Q tile transposed & pre-scaled by 1/sqrt(DH)=0.125
#pragma unroll
    for (int it = 0; it < 4; it++) {
        int idx = it * 256 + tid;
        int r = idx >> 4, e0 = (idx & 15) * 4;
        float4 qv = *(const float4*)&Q[((size_t)(b * SSQ + q0 + r) * DDm) + h * DHH + e0];
        sQt[(e0 + 0) * ATP + r] = qv.x * 0.125f;
        sQt[(e0 + 1) * ATP + r] = qv.y * 0.125f;
        sQt[(e0 + 2) * ATP + r] = qv.z * 0.125f;
        sQt[(e0 + 3) * ATP + r] = qv.w * 0.125f;
    }

    float m[4], l[4], o[4][4];
#pragma unroll
    for (int i = 0; i < 4; i++) {
        m[i] = -1e30f; l[i] = 0.0f;
#pragma unroll
        for (int j = 0; j < 4; j++) o[i][j] = 0.0f;
    }

    for (int kv0 = 0; kv0 < SSQ; kv0 += 64) {
        __syncthreads();  // previous iter readers done (also covers sQt readiness)
        // load K (transposed) and V (natural)
#pragma unroll
        for (int it = 0; it < 4; it++) {
            int idx = it * 256 + tid;
            int c = idx >> 4, e0 = (idx & 15) * 4;
            size_t base = ((size_t)(b * SSQ + kv0 + c) * DDm) + h * DHH + e0;
            float4 kvv = *(const float4*)&Kg[base];
            sKt[(e0 + 0) * ATP + c] = kvv.x;
            sKt[(e0 + 1) * ATP + c] = kvv.y;
            sKt[(e0 + 2) * ATP + c] = kvv.z;
            sKt[(e0 + 3) * ATP + c] = kvv.w;
            float4 vv = *(const float4*)&Vg[base];
            *(float4*)&sV[c * 64 + e0] = vv;
        }
        __syncthreads();

        // scores: s[i][j] = sum_e Qt[e][ty*4+i] * Kt[e][tx*4+j]
        float s[4][4];
#pragma unroll
        for (int i = 0; i < 4; i++)
#pragma unroll
            for (int j = 0; j < 4; j++) s[i][j] = 0.0f;

#pragma unroll 8
        for (int k = 0; k < 64; k++) {
            float4 qv = *(float4*)&sQt[k * ATP + ty * 4];
            float4 kv = *(float4*)&sKt[k * ATP + tx * 4];
            float qa[4] = {qv.x, qv.y, qv.z, qv.w};
            float ka[4] = {kv.x, kv.y, kv.z, kv.w};
#pragma unroll
            for (int i = 0; i < 4; i++)
#pragma unroll
                for (int j = 0; j < 4; j++)
                    s[i][j] += qa[i] * ka[j];
        }

        // online softmax update (row reductions over the 16 tx lanes)
#pragma unroll
        for (int i = 0; i < 4; i++) {
            float mx = fmaxf(fmaxf(s[i][0], s[i][1]), fmaxf(s[i][2], s[i][3]));
#pragma unroll
            for (int off = 1; off < 16; off <<= 1)
                mx = fmaxf(mx, __shfl_xor_sync(0xffffffffu, mx, off));
            float newm = fmaxf(m[i], mx);
            float corr = __expf(m[i] - newm);
            float p0 = __expf(s[i][0] - newm);
            float p1 = __expf(s[i][1] - newm);
            float p2 = __expf(s[i][2] - newm);
            float p3 = __expf(s[i][3] - newm);
            float sum = p0 + p1 + p2 + p3;
#pragma unroll
            for (int off = 1; off < 16; off <<= 1)
                sum += __shfl_xor_sync(0xffffffffu, sum, off);
            l[i] = l[i] * corr + sum;
            m[i] = newm;
#pragma unroll
            for (int j = 0; j < 4; j++) o[i][j] *= corr;
            s[i][0] = p0; s[i][1] = p1; s[i][2] = p2; s[i][3] = p3;
        }

        // write P transposed: sPt[c][r]
#pragma unroll
        for (int j = 0; j < 4; j++)
#pragma unroll
            for (int i = 0; i < 4; i++)
                sPt[(tx * 4 + j) * ATP + ty * 4 + i] = s[i][j];
        __syncthreads();

        // O += P @ V
#pragma unroll 8
        for (int kk = 0; kk < 64; kk++) {
            float4 pv = *(float4*)&sPt[kk * ATP + ty * 4];
            float4 vv = *(float4*)&sV[kk * 64 + tx * 4];
            float pa[4] = {pv.x, pv.y, pv.z, pv.w};
            float va[4] = {vv.x, vv.y, vv.z, vv.w};
#pragma unroll
            for (int i = 0; i < 4; i++)
#pragma unroll
                for (int j = 0; j < 4; j++)
                    o[i][j] += pa[i] * va[j];
        }
    }

    // finalize & store
#pragma unroll
    for (int i = 0; i < 4; i++) {
        float inv = 1.0f / l[i];
        float4 ov = make_float4(o[i][0] * inv, o[i][1] * inv, o[i][2] * inv, o[i][3] * inv);
        *(float4*)&CTX[((size_t)(b * SSQ + q0 + ty * 4 + i) * DDm) + h * DHH + tx * 4] = ov;
    }
}

// ---------------- LayerNorm: one row (D=1024) per block, 256 threads --------
__global__ __launch_bounds__(256)
void ln_k(const float* __restrict__ in, const float* __restrict__ w,
          const float* __restrict__ bb, float* __restrict__ out)
{
    __shared__ float red[34];
    const int row = blockIdx.x;
    const int tid = threadIdx.x;

    float4 x = *(const float4*)&in[(size_t)row * DDm + tid * 4];
    float s = x.x + x.y + x.z + x.w;
#pragma unroll
    for (int off = 16; off; off >>= 1) s += __shfl_xor_sync(0xffffffffu, s, off);
    if ((tid & 31) == 0) red[tid >> 5] = s;
    __syncthreads();
    if (tid == 0) {
        float t = 0.0f;
        for (int i = 0; i < 8; i++) t += red[i];
        red[32] = t;
    }
    __syncthreads();
    float mean = red[32] * (1.0f / DDm);

    float d0 = x.x - mean, d1 = x.y - mean, d2 = x.z - mean, d3 = x.w - mean;
    float sq = d0 * d0 + d1 * d1 + d2 * d2 + d3 * d3;
#pragma unroll
    for (int off = 16; off; off >>= 1) sq += __shfl_xor_sync(0xffffffffu, sq, off);
    if ((tid & 31) == 0) red[tid >> 5] = sq;
    __syncthreads();
    if (tid == 0) {
        float t = 0.0f;
        for (int i = 0; i < 8; i++) t += red[i];
        red[33] = t;
    }
    __syncthreads();
    float rs = rsqrtf(red[33] * (1.0f / DDm) + EPSLN);

    float4 wv = *(const float4*)&w[tid * 4];
    float4 bv = *(const float4*)&bb[tid * 4];
    float4 y;
    y.x = d0 * rs * wv.x + bv.x;
    y.y = d1 * rs * wv.y + bv.y;
    y.z = d2 * rs * wv.z + bv.z;
    y.w = d3 * rs * wv.w + bv.w;
    *(float4*)&out[(size_t)row * DDm + tid * 4] = y;
}

// ---------------------------- launch ---------------------------------------
extern "C" void kernel_launch(void* const* d_in, const int* in_sizes, int n_in,
                              void* d_out, int out_size)
{
    const float* src   = (const float*)d_in[0];
    const float* Wq    = (const float*)d_in[1];
    const float* bq    = (const float*)d_in[2];
    const float* Wk    = (const float*)d_in[3];
    const float* bk    = (const float*)d_in[4];
    const float* Wv    = (const float*)d_in[5];
    const float* bv    = (const float*)d_in[6];
    const float* Wo    = (const float*)d_in[7];
    const float* bo    = (const float*)d_in[8];
    const float* ln1w  = (const float*)d_in[9];
    const float* ln1b  = (const float*)d_in[10];
    const float* W1    = (const float*)d_in[11];
    const float* b1    = (const float*)d_in[12];
    const float* W2    = (const float*)d_in[13];
    const float* b2    = (const float*)d_in[14];
    const float* ln2w  = (const float*)d_in[15];
    const float* ln2b  = (const float*)d_in[16];
    float* out = (float*)d_out;

    float *pq, *pk, *pv, *pctx, *py1, *px, *ph, *py2;
    cudaGetSymbolAddress((void**)&pq,   g_q);
    cudaGetSymbolAddress((void**)&pk,   g_k);
    cudaGetSymbolAddress((void**)&pv,   g_v);
    cudaGetSymbolAddress((void**)&pctx, g_ctx);
    cudaGetSymbolAddress((void**)&py1,  g_y1);
    cudaGetSymbolAddress((void**)&px,   g_x);
    cudaGetSymbolAddress((void**)&ph,   g_h);
    cudaGetSymbolAddress((void**)&py2,  g_y2);

    const int ATTN_SMEM = (3 * 64 * ATP + 64 * 64) * sizeof(float);
    cudaFuncSetAttribute(attn_k, cudaFuncAttributeMaxDynamicSharedMemorySize, ATTN_SMEM);

    dim3 thr(256);
    dim3 gQKV(DDm / 128, BSr / 128);     // (8, 64)
    dim3 gFFN1(FFd / 128, BSr / 128);    // (32, 64)

    // QKV projections
    gemm_k<1, 0, 0><<<gQKV, thr>>>(src, Wq, bq, nullptr, pq, BSr, DDm, DDm);
    gemm_k<1, 0, 0><<<gQKV, thr>>>(src, Wk, bk, nullptr, pk, BSr, DDm, DDm);
    gemm_k<1, 0, 0><<<gQKV, thr>>>(src, Wv, bv, nullptr, pv, BSr, DDm, DDm);

    // attention
    dim3 gAttn(SSQ / 64, HHn, BB);
    attn_k<<<gAttn, thr, ATTN_SMEM>>>(pq, pk, pv, pctx);

    // output projection + residual, LN1
    gemm_k<0, 0, 1><<<gQKV, thr>>>(pctx, Wo, bo, src, py1, BSr, DDm, DDm);
    ln_k<<<BSr, thr>>>(py1, ln1w, ln1b, px);

    // FFN
    gemm_k<0, 1, 0><<<gFFN1, thr>>>(px, W1, b1, nullptr, ph, BSr, FFd, DDm);
    gemm_k<0, 0, 1><<<gQKV, thr>>>(ph, W2, b2, px, py2, BSr, DDm, FFd);
    ln_k<<<BSr, thr>>>(py2, ln2w, ln2b, out);
}

// round 4
// speedup vs baseline: 3.6940x; 3.6940x over previous
#include <cuda_runtime.h>
#include <cuda_fp16.h>
#include <cstddef>
#include <cstdint>

// Problem constants
#define BB  4
#define SSQ 2048
#define DDm 1024
#define HHn 16
#define DHH 64
#define FFd 4096
#define BSr (BB*SSQ)      // 8192 rows
#define EPSLN 1e-5f

// ---------------- scratch (device globals; allocation-free) ----------------
__device__ float g_q  [BSr*DDm];
__device__ float g_k  [BSr*DDm];
__device__ float g_v  [BSr*DDm];
__device__ float g_ctx[BSr*DDm];
__device__ float g_y1 [BSr*DDm];
__device__ float g_x  [BSr*DDm];
__device__ float g_y2 [BSr*DDm];

__device__ __half g_src16[BSr*DDm];
__device__ __half g_ctx16[BSr*DDm];
__device__ __half g_x16  [BSr*DDm];
__device__ __half g_h16  [(size_t)BSr*FFd];

__device__ __half g_wqT[DDm*DDm];
__device__ __half g_wkT[DDm*DDm];
__device__ __half g_wvT[DDm*DDm];
__device__ __half g_woT[DDm*DDm];
__device__ __half g_w1T[(size_t)DDm*FFd];
__device__ __half g_w2T[(size_t)DDm*FFd];

// ---------------- cp.async helpers -----------------------------------------
#define CP_ASYNC16(dst, src) \
    asm volatile("cp.async.cg.shared.global [%0], [%1], 16;\n" :: "r"(dst), "l"(src))
#define CP_COMMIT() asm volatile("cp.async.commit_group;\n" ::)
#define CP_WAIT1()  asm volatile("cp.async.wait_group 1;\n" ::)

#define MMA16816(d, a, b0, b1) \
    asm volatile("mma.sync.aligned.m16n8k16.row.col.f32.f16.f16.f32 " \
        "{%0,%1,%2,%3},{%4,%5,%6,%7},{%8,%9},{%0,%1,%2,%3};\n" \
        : "+f"(d[0]), "+f"(d[1]), "+f"(d[2]), "+f"(d[3]) \
        : "r"(a[0]), "r"(a[1]), "r"(a[2]), "r"(a[3]), "r"(b0), "r"(b1))

// ---------------- fp16 HGEMM: C[M,N] = A16[M,K] @ Bt16[N,K]^T ---------------
// + bias (+res fp32)(relu). Outputs fp32 and/or fp16.
// Tiles: CTA 128x128, 8 warps of 32x64, BK=32, double-buffered cp.async.
#define SROW 40   // smem row stride in halves (20 b32) -> conflict-free frags
template<int RELU, int RES, int OUT32, int OUT16>
__global__ __launch_bounds__(256)
void hgemm_k(const __half* __restrict__ A, const __half* __restrict__ Bt,
             const float* __restrict__ bias, const float* __restrict__ res,
             float* __restrict__ C32, __half* __restrict__ C16,
             int M, int N, int K)
{
    __shared__ __half As[2][128 * SROW];
    __shared__ __half Bs[2][128 * SROW];

    const int tid  = threadIdx.x;
    const int warp = tid >> 5;
    const int lane = tid & 31;
    const int wm = (warp >> 1) * 32;
    const int wn = (warp & 1) * 64;
    const int bm = blockIdx.y * 128;
    const int bn = blockIdx.x * 128;

    // loaders: 2 threads per row, 16 halves (2 x 16B) each
    const int lrow  = tid >> 1;
    const int lcolh = (tid & 1) * 16;

    const __half* Ag = A  + (size_t)(bm + lrow) * K + lcolh;
    const __half* Bg = Bt + (size_t)(bn + lrow) * K + lcolh;

    unsigned saA[2], saB[2];
#pragma unroll
    for (int b = 0; b < 2; b++) {
        saA[b] = (unsigned)__cvta_generic_to_shared(&As[b][lrow * SROW + lcolh]);
        saB[b] = (unsigned)__cvta_generic_to_shared(&Bs[b][lrow * SROW + lcolh]);
    }

    float acc[2][8][4];
#pragma unroll
    for (int mt = 0; mt < 2; mt++)
#pragma unroll
        for (int nt = 0; nt < 8; nt++)
#pragma unroll
            for (int i = 0; i < 4; i++) acc[mt][nt][i] = 0.0f;

    const int r  = lane >> 2;
    const int cb = lane & 3;
    const int niter = K >> 5;

    // prologue: tile 0 -> buf 0  (second 16B chunk: +8 halves = +16 BYTES)
    CP_ASYNC16(saA[0],      Ag);
    CP_ASYNC16(saA[0] + 16, Ag + 8);
    CP_ASYNC16(saB[0],      Bg);
    CP_ASYNC16(saB[0] + 16, Bg + 8);
    CP_COMMIT();

    for (int kt = 0; kt < niter; kt++) {
        const int cbuf = kt & 1;
        const int nbuf = cbuf ^ 1;
        if (kt + 1 < niter) {
            int k0 = (kt + 1) << 5;
            CP_ASYNC16(saA[nbuf],      Ag + k0);
            CP_ASYNC16(saA[nbuf] + 16, Ag + k0 + 8);
            CP_ASYNC16(saB[nbuf],      Bg + k0);
            CP_ASYNC16(saB[nbuf] + 16, Bg + k0 + 8);
        }
        CP_COMMIT();
        CP_WAIT1();
        __syncthreads();

        const uint32_t* Ab = (const uint32_t*)As[cbuf];
        const uint32_t* Bb = (const uint32_t*)Bs[cbuf];
#pragma unroll
        for (int s = 0; s < 2; s++) {
            uint32_t af[2][4];
#pragma unroll
            for (int mt = 0; mt < 2; mt++) {
                int base = (wm + mt * 16 + r) * 20 + s * 8 + cb;
                af[mt][0] = Ab[base];
                af[mt][1] = Ab[base + 160];       // +8 rows
                af[mt][2] = Ab[base + 4];         // k+8
                af[mt][3] = Ab[base + 164];
            }
#pragma unroll
            for (int nt = 0; nt < 8; nt++) {
                int nb = (wn + nt * 8 + r) * 20 + s * 8 + cb;
                uint32_t b0 = Bb[nb];
                uint32_t b1 = Bb[nb + 4];
                MMA16816(acc[0][nt], af[0], b0, b1);
                MMA16816(acc[1][nt], af[1], b0, b1);
            }
        }
        __syncthreads();
    }

    // epilogue
#pragma unroll
    for (int mt = 0; mt < 2; mt++) {
#pragma unroll
        for (int hh = 0; hh < 2; hh++) {
            int row = bm + wm + mt * 16 + r + hh * 8;
#pragma unroll
            for (int nt = 0; nt < 8; nt++) {
                int col = bn + wn + nt * 8 + cb * 2;
                float v0 = acc[mt][nt][hh * 2 + 0] + bias[col];
                float v1 = acc[mt][nt][hh * 2 + 1] + bias[col + 1];
                if (RES) {
                    float2 rv = *(const float2*)&res[(size_t)row * N + col];
                    v0 += rv.x; v1 += rv.y;
                }
                if (RELU) { v0 = fmaxf(v0, 0.0f); v1 = fmaxf(v1, 0.0f); }
                if (OUT32) {
                    *(float2*)&C32[(size_t)row * N + col] = make_float2(v0, v1);
                }
                if (OUT16) {
                    *(__half2*)&C16[(size_t)row * N + col] =
                        __floats2half2_rn(v0, v1);
                }
            }
        }
    }
}

// ---------------- transpose + convert: in[K][N] f32 -> out[N][K] f16 --------
// batched over blockIdx.z (in += z*K*N, out += z*N*K rows offset z*N)
__global__ __launch_bounds__(256)
void tconv_k(const float* __restrict__ in, __half* __restrict__ out,
             int Kd, int Nd)
{
    __shared__ float t[32][33];
    const int z = blockIdx.z;
    const float* inb = in + (size_t)z * Kd * Nd;
    __half* outb = out + (size_t)z * Nd * Kd;
    const int n0 = blockIdx.x * 32, k0 = blockIdx.y * 32;
    const int tx = threadIdx.x & 31, ty = threadIdx.x >> 5;

#pragma unroll
    for (int i = ty; i < 32; i += 8)
        t[i][tx] = inb[(size_t)(k0 + i) * Nd + n0 + tx];
    __syncthreads();
#pragma unroll
    for (int i = ty; i < 32; i += 8)
        outb[(size_t)(n0 + i) * Kd + k0 + tx] = __float2half_rn(t[tx][i]);
}

// ---------------- elementwise f32 -> f16 ------------------------------------
__global__ __launch_bounds__(256)
void conv16_k(const float4* __restrict__ in, __half2* __restrict__ out, int n4)
{
    int i = blockIdx.x * 256 + threadIdx.x;
    if (i < n4) {
        float4 v = in[i];
        out[i * 2 + 0] = __floats2half2_rn(v.x, v.y);
        out[i * 2 + 1] = __floats2half2_rn(v.z, v.w);
    }
}

// ---------------- flash attention (fp32), 64x64 tiles, online softmax -------
#define ATP 68
__global__ __launch_bounds__(256)
void attn_k(const float* __restrict__ Q, const float* __restrict__ Kg,
            const float* __restrict__ Vg, float* __restrict__ CTX)
{
    extern __shared__ float sm[];
    float* sQt = sm;
    float* sKt = sm + 64 * ATP;
    float* sV  = sm + 2 * 64 * ATP;
    float* sPt = sm + 2 * 64 * ATP + 64 * 64;

    const int b = blockIdx.z, h = blockIdx.y;
    const int q0 = blockIdx.x * 64;
    const int tid = threadIdx.x;
    const int tx = tid & 15, ty = tid >> 4;

#pragma unroll
    for (int it = 0; it < 4; it++) {
        int idx = it * 256 + tid;
        int rr = idx >> 4, e0 = (idx & 15) * 4;
        float4 qv = *(const float4*)&Q[((size_t)(b * SSQ + q0 + rr) * DDm) + h * DHH + e0];
        sQt[(e0 + 0) * ATP + rr] = qv.x * 0.125f;
        sQt[(e0 + 1) * ATP + rr] = qv.y * 0.125f;
        sQt[(e0 + 2) * ATP + rr] = qv.z * 0.125f;
        sQt[(e0 + 3) * ATP + rr] = qv.w * 0.125f;
    }

    float m[4], l[4], o[4][4];
#pragma unroll
    for (int i = 0; i < 4; i++) {
        m[i] = -1e30f; l[i] = 0.0f;
#pragma unroll
        for (int j = 0; j < 4; j++) o[i][j] = 0.0f;
    }

    for (int kv0 = 0; kv0 < SSQ; kv0 += 64) {
        __syncthreads();
#pragma unroll
        for (int it = 0; it < 4; it++) {
            int idx = it * 256 + tid;
            int c = idx >> 4, e0 = (idx & 15) * 4;
            size_t base = ((size_t)(b * SSQ + kv0 + c) * DDm) + h * DHH + e0;
            float4 kvv = *(const float4*)&Kg[base];
            sKt[(e0 + 0) * ATP + c] = kvv.x;
            sKt[(e0 + 1) * ATP + c] = kvv.y;
            sKt[(e0 + 2) * ATP + c] = kvv.z;
            sKt[(e0 + 3) * ATP + c] = kvv.w;
            float4 vv = *(const float4*)&Vg[base];
            *(float4*)&sV[c * 64 + e0] = vv;
        }
        __syncthreads();

        float s[4][4];
#pragma unroll
        for (int i = 0; i < 4; i++)
#pragma unroll
            for (int j = 0; j < 4; j++) s[i][j] = 0.0f;

#pragma unroll 8
        for (int k = 0; k < 64; k++) {
            float4 qv = *(float4*)&sQt[k * ATP + ty * 4];
            float4 kv = *(float4*)&sKt[k * ATP + tx * 4];
            float qa[4] = {qv.x, qv.y, qv.z, qv.w};
            float ka[4] = {kv.x, kv.y, kv.z, kv.w};
#pragma unroll
            for (int i = 0; i < 4; i++)
#pragma unroll
                for (int j = 0; j < 4; j++)
                    s[i][j] += qa[i] * ka[j];
        }

#pragma unroll
        for (int i = 0; i < 4; i++) {
            float mx = fmaxf(fmaxf(s[i][0], s[i][1]), fmaxf(s[i][2], s[i][3]));
#pragma unroll
            for (int off = 1; off < 16; off <<= 1)
                mx = fmaxf(mx, __shfl_xor_sync(0xffffffffu, mx, off));
            float newm = fmaxf(m[i], mx);
            float corr = __expf(m[i] - newm);
            float p0 = __expf(s[i][0] - newm);
            float p1 = __expf(s[i][1] - newm);
            float p2 = __expf(s[i][2] - newm);
            float p3 = __expf(s[i][3] - newm);
            float sum = p0 + p1 + p2 + p3;
#pragma unroll
            for (int off = 1; off < 16; off <<= 1)
                sum += __shfl_xor_sync(0xffffffffu, sum, off);
            l[i] = l[i] * corr + sum;
            m[i] = newm;
#pragma unroll
            for (int j = 0; j < 4; j++) o[i][j] *= corr;
            s[i][0] = p0; s[i][1] = p1; s[i][2] = p2; s[i][3] = p3;
        }

#pragma unroll
        for (int j = 0; j < 4; j++)
#pragma unroll
            for (int i = 0; i < 4; i++)
                sPt[(tx * 4 + j) * ATP + ty * 4 + i] = s[i][j];
        __syncthreads();

#pragma unroll 8
        for (int kk = 0; kk < 64; kk++) {
            float4 pv = *(float4*)&sPt[kk * ATP + ty * 4];
            float4 vv = *(float4*)&sV[kk * 64 + tx * 4];
            float pa[4] = {pv.x, pv.y, pv.z, pv.w};
            float va[4] = {vv.x, vv.y, vv.z, vv.w};
#pragma unroll
            for (int i = 0; i < 4; i++)
#pragma unroll
                for (int j = 0; j < 4; j++)
                    o[i][j] += pa[i] * va[j];
        }
    }

#pragma unroll
    for (int i = 0; i < 4; i++) {
        float inv = 1.0f / l[i];
        float4 ov = make_float4(o[i][0] * inv, o[i][1] * inv, o[i][2] * inv, o[i][3] * inv);
        *(float4*)&CTX[((size_t)(b * SSQ + q0 + ty * 4 + i) * DDm) + h * DHH + tx * 4] = ov;
    }
}

// ---------------- LayerNorm: one row per block, optional fp16 copy ----------
template<int OUT16>
__global__ __launch_bounds__(256)
void ln_k(const float* __restrict__ in, const float* __restrict__ w,
          const float* __restrict__ bb, float* __restrict__ out32,
          __half* __restrict__ out16)
{
    __shared__ float red[34];
    const int row = blockIdx.x;
    const int tid = threadIdx.x;

    float4 x = *(const float4*)&in[(size_t)row * DDm + tid * 4];
    float s = x.x + x.y + x.z + x.w;
#pragma unroll
    for (int off = 16; off; off >>= 1) s += __shfl_xor_sync(0xffffffffu, s, off);
    if ((tid & 31) == 0) red[tid >> 5] = s;
    __syncthreads();
    if (tid == 0) {
        float t = 0.0f;
        for (int i = 0; i < 8; i++) t += red[i];
        red[32] = t;
    }
    __syncthreads();
    float mean = red[32] * (1.0f / DDm);

    float d0 = x.x - mean, d1 = x.y - mean, d2 = x.z - mean, d3 = x.w - mean;
    float sq = d0 * d0 + d1 * d1 + d2 * d2 + d3 * d3;
#pragma unroll
    for (int off = 16; off; off >>= 1) sq += __shfl_xor_sync(0xffffffffu, sq, off);
    if ((tid & 31) == 0) red[tid >> 5] = sq;
    __syncthreads();
    if (tid == 0) {
        float t = 0.0f;
        for (int i = 0; i < 8; i++) t += red[i];
        red[33] = t;
    }
    __syncthreads();
    float rs = rsqrtf(red[33] * (1.0f / DDm) + EPSLN);

    float4 wv = *(const float4*)&w[tid * 4];
    float4 bv = *(const float4*)&bb[tid * 4];
    float y0 = d0 * rs * wv.x + bv.x;
    float y1 = d1 * rs * wv.y + bv.y;
    float y2 = d2 * rs * wv.z + bv.z;
    float y3 = d3 * rs * wv.w + bv.w;
    *(float4*)&out32[(size_t)row * DDm + tid * 4] = make_float4(y0, y1, y2, y3);
    if (OUT16) {
        *(__half2*)&out16[(size_t)row * DDm + tid * 4 + 0] = __floats2half2_rn(y0, y1);
        *(__half2*)&out16[(size_t)row * DDm + tid * 4 + 2] = __floats2half2_rn(y2, y3);
    }
}

// ---------------------------- launch ---------------------------------------
extern "C" void kernel_launch(void* const* d_in, const int* in_sizes, int n_in,
                              void* d_out, int out_size)
{
    const float* src   = (const float*)d_in[0];
    const float* Wq    = (const float*)d_in[1];
    const float* bq    = (const float*)d_in[2];
    const float* Wk    = (const float*)d_in[3];
    const float* bk    = (const float*)d_in[4];
    const float* Wv    = (const float*)d_in[5];
    const float* bv    = (const float*)d_in[6];
    const float* Wo    = (const float*)d_in[7];
    const float* bo    = (const float*)d_in[8];
    const float* ln1w  = (const float*)d_in[9];
    const float* ln1b  = (const float*)d_in[10];
    const float* W1    = (const float*)d_in[11];
    const float* b1    = (const float*)d_in[12];
    const float* W2    = (const float*)d_in[13];
    const float* b2    = (const float*)d_in[14];
    const float* ln2w  = (const float*)d_in[15];
    const float* ln2b  = (const float*)d_in[16];
    float* out = (float*)d_out;

    float *pq, *pk, *pv, *pctx, *py1, *px, *py2;
    __half *psrc16, *pctx16, *px16, *ph16;
    __half *pwqT, *pwkT, *pwvT, *pwoT, *pw1T, *pw2T;
    cudaGetSymbolAddress((void**)&pq,    g_q);
    cudaGetSymbolAddress((void**)&pk,    g_k);
    cudaGetSymbolAddress((void**)&pv,    g_v);
    cudaGetSymbolAddress((void**)&pctx,  g_ctx);
    cudaGetSymbolAddress((void**)&py1,   g_y1);
    cudaGetSymbolAddress((void**)&px,    g_x);
    cudaGetSymbolAddress((void**)&py2,   g_y2);
    cudaGetSymbolAddress((void**)&psrc16, g_src16);
    cudaGetSymbolAddress((void**)&pctx16, g_ctx16);
    cudaGetSymbolAddress((void**)&px16,   g_x16);
    cudaGetSymbolAddress((void**)&ph16,   g_h16);
    cudaGetSymbolAddress((void**)&pwqT,   g_wqT);
    cudaGetSymbolAddress((void**)&pwkT,   g_wkT);
    cudaGetSymbolAddress((void**)&pwvT,   g_wvT);
    cudaGetSymbolAddress((void**)&pwoT,   g_woT);
    cudaGetSymbolAddress((void**)&pw1T,   g_w1T);
    cudaGetSymbolAddress((void**)&pw2T,   g_w2T);

    const int ATTN_SMEM = (3 * 64 * ATP + 64 * 64) * sizeof(float);
    cudaFuncSetAttribute(attn_k, cudaFuncAttributeMaxDynamicSharedMemorySize, ATTN_SMEM);

    dim3 thr(256);

    // ---- weight transpose+convert (fp32 -> fp16 [N][K]) ----
    tconv_k<<<dim3(2, 32, 16), thr>>>(Wq, pwqT, DDm, DHH);      // [H][D][DH] -> [1024][1024]
    tconv_k<<<dim3(2, 32, 16), thr>>>(Wk, pwkT, DDm, DHH);
    tconv_k<<<dim3(2, 32, 16), thr>>>(Wv, pwvT, DDm, DHH);
    tconv_k<<<dim3(32, 32, 1), thr>>>(Wo, pwoT, DDm, DDm);      // [1024][1024]
    tconv_k<<<dim3(128, 32, 1), thr>>>(W1, pw1T, DDm, FFd);     // [1024][4096] -> [4096][1024]
    tconv_k<<<dim3(32, 128, 1), thr>>>(W2, pw2T, FFd, DDm);     // [4096][1024] -> [1024][4096]

    // ---- src -> fp16 ----
    conv16_k<<<(BSr * DDm / 4 + 255) / 256, thr>>>((const float4*)src, (__half2*)psrc16, BSr * DDm / 4);

    // ---- QKV projections (fp16 MMA, fp32 out) ----
    dim3 gD(DDm / 128, BSr / 128);     // (8, 64)
    dim3 gF(FFd / 128, BSr / 128);     // (32, 64)
    hgemm_k<0, 0, 1, 0><<<gD, thr>>>(psrc16, pwqT, bq, nullptr, pq, nullptr, BSr, DDm, DDm);
    hgemm_k<0, 0, 1, 0><<<gD, thr>>>(psrc16, pwkT, bk, nullptr, pk, nullptr, BSr, DDm, DDm);
    hgemm_k<0, 0, 1, 0><<<gD, thr>>>(psrc16, pwvT, bv, nullptr, pv, nullptr, BSr, DDm, DDm);

    // ---- attention (fp32) ----
    dim3 gAttn(SSQ / 64, HHn, BB);
    attn_k<<<gAttn, thr, ATTN_SMEM>>>(pq, pk, pv, pctx);
    conv16_k<<<(BSr * DDm / 4 + 255) / 256, thr>>>((const float4*)pctx, (__half2*)pctx16, BSr * DDm / 4);

    // ---- output projection + residual, LN1 ----
    hgemm_k<0, 1, 1, 0><<<gD, thr>>>(pctx16, pwoT, bo, src, py1, nullptr, BSr, DDm, DDm);
    ln_k<1><<<BSr, thr>>>(py1, ln1w, ln1b, px, px16);

    // ---- FFN ----
    hgemm_k<1, 0, 0, 1><<<gF, thr>>>(px16, pw1T, b1, nullptr, nullptr, ph16, BSr, FFd, DDm);
    hgemm_k<0, 1, 1, 0><<<gD, thr>>>(ph16, pw2T, b2, px, py2, nullptr, BSr, DDm, FFd);
    ln_k<0><<<BSr, thr>>>(py2, ln2w, ln2b, out, nullptr);
}

// round 5
// speedup vs baseline: 8.5460x; 2.3135x over previous
#include <cuda_runtime.h>
#include <cuda_fp16.h>
#include <cstddef>
#include <cstdint>

// Problem constants
#define BB  4
#define SSQ 2048
#define DDm 1024
#define HHn 16
#define DHH 64
#define FFd 4096
#define BSr (BB*SSQ)      // 8192 rows
#define EPSLN 1e-5f

// ---------------- scratch (device globals; allocation-free) ----------------
__device__ float g_y1 [BSr*DDm];
__device__ float g_x  [BSr*DDm];
__device__ float g_y2 [BSr*DDm];

__device__ __half g_src16[BSr*DDm];
__device__ __half g_q16  [BSr*DDm];
__device__ __half g_k16  [BSr*DDm];
__device__ __half g_vT16 [(size_t)DDm*BSr];   // [n=h*64+dh][m=b*2048+s]
__device__ __half g_ctx16[BSr*DDm];
__device__ __half g_x16  [BSr*DDm];
__device__ __half g_h16  [(size_t)BSr*FFd];

__device__ __half g_wqT[DDm*DDm];
__device__ __half g_wkT[DDm*DDm];
__device__ __half g_wvT[DDm*DDm];
__device__ __half g_woT[DDm*DDm];
__device__ __half g_w1T[(size_t)DDm*FFd];
__device__ __half g_w2T[(size_t)DDm*FFd];

// ---------------- cp.async helpers -----------------------------------------
#define CP_ASYNC16(dst, src) \
    asm volatile("cp.async.cg.shared.global [%0], [%1], 16;\n" :: "r"(dst), "l"(src))
#define CP_COMMIT() asm volatile("cp.async.commit_group;\n" ::)
#define CP_WAIT1()  asm volatile("cp.async.wait_group 1;\n" ::)

#define MMA16816(d, a, b0, b1) \
    asm volatile("mma.sync.aligned.m16n8k16.row.col.f32.f16.f16.f32 " \
        "{%0,%1,%2,%3},{%4,%5,%6,%7},{%8,%9},{%0,%1,%2,%3};\n" \
        : "+f"(d[0]), "+f"(d[1]), "+f"(d[2]), "+f"(d[3]) \
        : "r"(a[0]), "r"(a[1]), "r"(a[2]), "r"(a[3]), "r"(b0), "r"(b1))

// ---------------- fp16 HGEMM: C[M,N] = A16[M,K] @ Bt16[N,K]^T ---------------
// + bias (+res fp32)(relu). Outputs fp32 / fp16 / fp16-transposed [N][M].
#define SROW 40   // smem row stride in halves (20 b32) -> conflict-free frags
template<int RELU, int RES, int OUT32, int OUT16, int OUT16T>
__global__ __launch_bounds__(256)
void hgemm_k(const __half* __restrict__ A, const __half* __restrict__ Bt,
             const float* __restrict__ bias, const float* __restrict__ res,
             float* __restrict__ C32, __half* __restrict__ C16,
             int M, int N, int K)
{
    __shared__ __half As[2][128 * SROW];
    __shared__ __half Bs[2][128 * SROW];

    const int tid  = threadIdx.x;
    const int warp = tid >> 5;
    const int lane = tid & 31;
    const int wm = (warp >> 1) * 32;
    const int wn = (warp & 1) * 64;
    const int bm = blockIdx.y * 128;
    const int bn = blockIdx.x * 128;

    const int lrow  = tid >> 1;
    const int lcolh = (tid & 1) * 16;

    const __half* Ag = A  + (size_t)(bm + lrow) * K + lcolh;
    const __half* Bg = Bt + (size_t)(bn + lrow) * K + lcolh;

    unsigned saA[2], saB[2];
#pragma unroll
    for (int b = 0; b < 2; b++) {
        saA[b] = (unsigned)__cvta_generic_to_shared(&As[b][lrow * SROW + lcolh]);
        saB[b] = (unsigned)__cvta_generic_to_shared(&Bs[b][lrow * SROW + lcolh]);
    }

    float acc[2][8][4];
#pragma unroll
    for (int mt = 0; mt < 2; mt++)
#pragma unroll
        for (int nt = 0; nt < 8; nt++)
#pragma unroll
            for (int i = 0; i < 4; i++) acc[mt][nt][i] = 0.0f;

    const int r  = lane >> 2;
    const int cb = lane & 3;
    const int niter = K >> 5;

    CP_ASYNC16(saA[0],      Ag);
    CP_ASYNC16(saA[0] + 16, Ag + 8);
    CP_ASYNC16(saB[0],      Bg);
    CP_ASYNC16(saB[0] + 16, Bg + 8);
    CP_COMMIT();

    for (int kt = 0; kt < niter; kt++) {
        const int cbuf = kt & 1;
        const int nbuf = cbuf ^ 1;
        if (kt + 1 < niter) {
            int k0 = (kt + 1) << 5;
            CP_ASYNC16(saA[nbuf],      Ag + k0);
            CP_ASYNC16(saA[nbuf] + 16, Ag + k0 + 8);
            CP_ASYNC16(saB[nbuf],      Bg + k0);
            CP_ASYNC16(saB[nbuf] + 16, Bg + k0 + 8);
        }
        CP_COMMIT();
        CP_WAIT1();
        __syncthreads();

        const uint32_t* Ab = (const uint32_t*)As[cbuf];
        const uint32_t* Bb = (const uint32_t*)Bs[cbuf];
#pragma unroll
        for (int s = 0; s < 2; s++) {
            uint32_t af[2][4];
#pragma unroll
            for (int mt = 0; mt < 2; mt++) {
                int base = (wm + mt * 16 + r) * 20 + s * 8 + cb;
                af[mt][0] = Ab[base];
                af[mt][1] = Ab[base + 160];
                af[mt][2] = Ab[base + 4];
                af[mt][3] = Ab[base + 164];
            }
#pragma unroll
            for (int nt = 0; nt < 8; nt++) {
                int nb = (wn + nt * 8 + r) * 20 + s * 8 + cb;
                uint32_t b0 = Bb[nb];
                uint32_t b1 = Bb[nb + 4];
                MMA16816(acc[0][nt], af[0], b0, b1);
                MMA16816(acc[1][nt], af[1], b0, b1);
            }
        }
        __syncthreads();
    }

#pragma unroll
    for (int mt = 0; mt < 2; mt++) {
#pragma unroll
        for (int hh = 0; hh < 2; hh++) {
            int row = bm + wm + mt * 16 + r + hh * 8;
#pragma unroll
            for (int nt = 0; nt < 8; nt++) {
                int col = bn + wn + nt * 8 + cb * 2;
                float v0 = acc[mt][nt][hh * 2 + 0] + bias[col];
                float v1 = acc[mt][nt][hh * 2 + 1] + bias[col + 1];
                if (RES) {
                    float2 rv = *(const float2*)&res[(size_t)row * N + col];
                    v0 += rv.x; v1 += rv.y;
                }
                if (RELU) { v0 = fmaxf(v0, 0.0f); v1 = fmaxf(v1, 0.0f); }
                if (OUT32)
                    *(float2*)&C32[(size_t)row * N + col] = make_float2(v0, v1);
                if (OUT16)
                    *(__half2*)&C16[(size_t)row * N + col] = __floats2half2_rn(v0, v1);
                if (OUT16T) {
                    C16[(size_t)col       * M + row] = __float2half_rn(v0);
                    C16[(size_t)(col + 1) * M + row] = __float2half_rn(v1);
                }
            }
        }
    }
}

// ---------------- transpose + convert: in[K][N] f32 -> out[N][K] f16 --------
__global__ __launch_bounds__(256)
void tconv_k(const float* __restrict__ in, __half* __restrict__ out,
             int Kd, int Nd)
{
    __shared__ float t[32][33];
    const int z = blockIdx.z;
    const float* inb = in + (size_t)z * Kd * Nd;
    __half* outb = out + (size_t)z * Nd * Kd;
    const int n0 = blockIdx.x * 32, k0 = blockIdx.y * 32;
    const int tx = threadIdx.x & 31, ty = threadIdx.x >> 5;

#pragma unroll
    for (int i = ty; i < 32; i += 8)
        t[i][tx] = inb[(size_t)(k0 + i) * Nd + n0 + tx];
    __syncthreads();
#pragma unroll
    for (int i = ty; i < 32; i += 8)
        outb[(size_t)(n0 + i) * Kd + k0 + tx] = __float2half_rn(t[tx][i]);
}

// ---------------- elementwise f32 -> f16 ------------------------------------
__global__ __launch_bounds__(256)
void conv16_k(const float4* __restrict__ in, __half2* __restrict__ out, int n4)
{
    int i = blockIdx.x * 256 + threadIdx.x;
    if (i < n4) {
        float4 v = in[i];
        out[i * 2 + 0] = __floats2half2_rn(v.x, v.y);
        out[i * 2 + 1] = __floats2half2_rn(v.z, v.w);
    }
}

// ---------------- fp16 tensor-core flash attention --------------------------
// CTA: 128 q rows for one (b,h). 8 warps x 16 rows. KV tiles of 64, double buf.
// Q,K: [token][1024] fp16 (head slice). V: transposed [h*64+dh][b*2048+s].
// smem rows padded to 36 b32 (72 halves).
#define KROW 36
__global__ __launch_bounds__(256)
void fattn_k(const __half* __restrict__ Qg, const __half* __restrict__ Kg,
             const __half* __restrict__ Vt, __half* __restrict__ CTX)
{
    extern __shared__ uint32_t dsm[];
    uint32_t* sQ = dsm;                       // 128*36
    uint32_t* sK = dsm + 128 * KROW;          // 2 * 64*36
    uint32_t* sV = dsm + 128 * KROW + 2 * 64 * KROW;

    const int b = blockIdx.z, h = blockIdx.y;
    const int q0 = blockIdx.x * 128;
    const int tid = threadIdx.x;
    const int warp = tid >> 5, lane = tid & 31;
    const int g = lane >> 2, t = lane & 3;

    // K/V tile loader mapping: row = tid>>2, half off = (tid&3)*16 -> 2x16B
    const int krow = tid >> 2;
    const int keh  = (tid & 3) * 16;     // halves
    const int keb  = (tid & 3) * 8;      // b32

    // ---- prologue: Q + tile0 (group), tile1 (group) ----
    {
        int row = tid >> 1, e0 = (tid & 1) * 32;
        const __half* src = Qg + (size_t)(b * SSQ + q0 + row) * DDm + h * DHH + e0;
        uint32_t dst = (uint32_t)__cvta_generic_to_shared(&sQ[row * KROW + (tid & 1) * 16]);
        CP_ASYNC16(dst,      src);
        CP_ASYNC16(dst + 16, src + 8);
        CP_ASYNC16(dst + 32, src + 16);
        CP_ASYNC16(dst + 48, src + 24);
    }
#define LOAD_TILE(buf, kv0) do { \
        uint32_t dk = (uint32_t)__cvta_generic_to_shared(&sK[(buf) * 64 * KROW + krow * KROW + keb]); \
        const __half* ks = Kg + (size_t)(b * SSQ + (kv0) + krow) * DDm + h * DHH + keh; \
        CP_ASYNC16(dk,      ks); \
        CP_ASYNC16(dk + 16, ks + 8); \
        uint32_t dv = (uint32_t)__cvta_generic_to_shared(&sV[(buf) * 64 * KROW + krow * KROW + keb]); \
        const __half* vs = Vt + (size_t)(h * DHH + krow) * BSr + (size_t)b * SSQ + (kv0) + keh; \
        CP_ASYNC16(dv,      vs); \
        CP_ASYNC16(dv + 16, vs + 8); \
    } while (0)

    LOAD_TILE(0, 0);
    CP_COMMIT();
    LOAD_TILE(1, 64);
    CP_COMMIT();

    CP_WAIT1();
    __syncthreads();

    // ---- Q fragments (persist in regs), scaled by 1/sqrt(64)=0.125 ----
    uint32_t qa[4][4];
    {
        const uint32_t* sQw = sQ + (warp * 16) * KROW;
        const __half2 sc = __float2half2_rn(0.125f);
#pragma unroll
        for (int kc = 0; kc < 4; kc++) {
            int base = g * KROW + kc * 8 + t;
            qa[kc][0] = sQw[base];
            qa[kc][1] = sQw[base + 8 * KROW];
            qa[kc][2] = sQw[base + 4];
            qa[kc][3] = sQw[base + 8 * KROW + 4];
#pragma unroll
            for (int i = 0; i < 4; i++) {
                __half2 v = __hmul2(*(__half2*)&qa[kc][i], sc);
                qa[kc][i] = *(uint32_t*)&v;
            }
        }
    }

    float m0 = -1e30f, m1 = -1e30f, l0 = 0.0f, l1 = 0.0f;
    float o[8][4];
#pragma unroll
    for (int n = 0; n < 8; n++)
#pragma unroll
        for (int i = 0; i < 4; i++) o[n][i] = 0.0f;

    const int NIT = SSQ / 64;     // 32
    for (int it = 0; it < NIT; it++) {
        const uint32_t* kb = sK + (it & 1) * 64 * KROW;
        const uint32_t* vb = sV + (it & 1) * 64 * KROW;

        // ---- S = Q @ K^T ----
        float acc[8][4];
#pragma unroll
        for (int n = 0; n < 8; n++)
#pragma unroll
            for (int i = 0; i < 4; i++) acc[n][i] = 0.0f;
#pragma unroll
        for (int kc = 0; kc < 4; kc++)
#pragma unroll
            for (int n = 0; n < 8; n++) {
                int base = (n * 8 + g) * KROW + kc * 8 + t;
                uint32_t b0 = kb[base];
                uint32_t b1 = kb[base + 4];
                MMA16816(acc[n], qa[kc], b0, b1);
            }

        // ---- online softmax (rows g and g+8) ----
        float mx0 = -1e30f, mx1 = -1e30f;
#pragma unroll
        for (int n = 0; n < 8; n++) {
            mx0 = fmaxf(mx0, fmaxf(acc[n][0], acc[n][1]));
            mx1 = fmaxf(mx1, fmaxf(acc[n][2], acc[n][3]));
        }
        mx0 = fmaxf(mx0, __shfl_xor_sync(0xffffffffu, mx0, 1));
        mx0 = fmaxf(mx0, __shfl_xor_sync(0xffffffffu, mx0, 2));
        mx1 = fmaxf(mx1, __shfl_xor_sync(0xffffffffu, mx1, 1));
        mx1 = fmaxf(mx1, __shfl_xor_sync(0xffffffffu, mx1, 2));
        float nm0 = fmaxf(m0, mx0), nm1 = fmaxf(m1, mx1);
        float c0 = __expf(m0 - nm0), c1 = __expf(m1 - nm1);

        uint32_t pa[4][4];
        float s0 = 0.0f, s1 = 0.0f;
#pragma unroll
        for (int n = 0; n < 8; n++) {
            float p00 = __expf(acc[n][0] - nm0);
            float p01 = __expf(acc[n][1] - nm0);
            float p10 = __expf(acc[n][2] - nm1);
            float p11 = __expf(acc[n][3] - nm1);
            s0 += p00 + p01;
            s1 += p10 + p11;
            __half2 h0 = __floats2half2_rn(p00, p01);
            __half2 h1 = __floats2half2_rn(p10, p11);
            if (n & 1) {
                pa[n >> 1][2] = *(uint32_t*)&h0;
                pa[n >> 1][3] = *(uint32_t*)&h1;
            } else {
                pa[n >> 1][0] = *(uint32_t*)&h0;
                pa[n >> 1][1] = *(uint32_t*)&h1;
            }
        }
        s0 += __shfl_xor_sync(0xffffffffu, s0, 1);
        s0 += __shfl_xor_sync(0xffffffffu, s0, 2);
        s1 += __shfl_xor_sync(0xffffffffu, s1, 1);
        s1 += __shfl_xor_sync(0xffffffffu, s1, 2);
        l0 = l0 * c0 + s0;
        l1 = l1 * c1 + s1;
        m0 = nm0; m1 = nm1;
#pragma unroll
        for (int n = 0; n < 8; n++) {
            o[n][0] *= c0; o[n][1] *= c0;
            o[n][2] *= c1; o[n][3] *= c1;
        }

        // ---- O += P @ V  (P fragments reused from S accumulators) ----
#pragma unroll
        for (int kc = 0; kc < 4; kc++)
#pragma unroll
            for (int n = 0; n < 8; n++) {
                int base = (n * 8 + g) * KROW + kc * 8 + t;
                uint32_t b0 = vb[base];
                uint32_t b1 = vb[base + 4];
                MMA16816(o[n], pa[kc], b0, b1);
            }

        __syncthreads();
        if (it + 2 < NIT) LOAD_TILE(it & 1, (it + 2) * 64);
        CP_COMMIT();
        if (it + 1 < NIT) { CP_WAIT1(); __syncthreads(); }
    }

    // ---- finalize + store fp16 ----
    float i0 = 1.0f / l0, i1 = 1.0f / l1;
    int r0 = b * SSQ + q0 + warp * 16 + g;
#pragma unroll
    for (int n = 0; n < 8; n++) {
        int col = h * DHH + n * 8 + t * 2;
        __half2 h0 = __floats2half2_rn(o[n][0] * i0, o[n][1] * i0);
        __half2 h1 = __floats2half2_rn(o[n][2] * i1, o[n][3] * i1);
        *(__half2*)&CTX[(size_t)r0 * DDm + col]       = h0;
        *(__half2*)&CTX[(size_t)(r0 + 8) * DDm + col] = h1;
    }
}

// ---------------- LayerNorm: one row per block, optional fp16 copy ----------
template<int OUT16>
__global__ __launch_bounds__(256)
void ln_k(const float* __restrict__ in, const float* __restrict__ w,
          const float* __restrict__ bb, float* __restrict__ out32,
          __half* __restrict__ out16)
{
    __shared__ float red[34];
    const int row = blockIdx.x;
    const int tid = threadIdx.x;

    float4 x = *(const float4*)&in[(size_t)row * DDm + tid * 4];
    float s = x.x + x.y + x.z + x.w;
#pragma unroll
    for (int off = 16; off; off >>= 1) s += __shfl_xor_sync(0xffffffffu, s, off);
    if ((tid & 31) == 0) red[tid >> 5] = s;
    __syncthreads();
    if (tid == 0) {
        float tt = 0.0f;
        for (int i = 0; i < 8; i++) tt += red[i];
        red[32] = tt;
    }
    __syncthreads();
    float mean = red[32] * (1.0f / DDm);

    float d0 = x.x - mean, d1 = x.y - mean, d2 = x.z - mean, d3 = x.w - mean;
    float sq = d0 * d0 + d1 * d1 + d2 * d2 + d3 * d3;
#pragma unroll
    for (int off = 16; off; off >>= 1) sq += __shfl_xor_sync(0xffffffffu, sq, off);
    if ((tid & 31) == 0) red[tid >> 5] = sq;
    __syncthreads();
    if (tid == 0) {
        float tt = 0.0f;
        for (int i = 0; i < 8; i++) tt += red[i];
        red[33] = tt;
    }
    __syncthreads();
    float rs = rsqrtf(red[33] * (1.0f / DDm) + EPSLN);

    float4 wv = *(const float4*)&w[tid * 4];
    float4 bv = *(const float4*)&bb[tid * 4];
    float y0 = d0 * rs * wv.x + bv.x;
    float y1 = d1 * rs * wv.y + bv.y;
    float y2 = d2 * rs * wv.z + bv.z;
    float y3 = d3 * rs * wv.w + bv.w;
    *(float4*)&out32[(size_t)row * DDm + tid * 4] = make_float4(y0, y1, y2, y3);
    if (OUT16) {
        *(__half2*)&out16[(size_t)row * DDm + tid * 4 + 0] = __floats2half2_rn(y0, y1);
        *(__half2*)&out16[(size_t)row * DDm + tid * 4 + 2] = __floats2half2_rn(y2, y3);
    }
}

// ---------------------------- launch ---------------------------------------
extern "C" void kernel_launch(void* const* d_in, const int* in_sizes, int n_in,
                              void* d_out, int out_size)
{
    const float* src   = (const float*)d_in[0];
    const float* Wq    = (const float*)d_in[1];
    const float* bq    = (const float*)d_in[2];
    const float* Wk    = (const float*)d_in[3];
    const float* bk    = (const float*)d_in[4];
    const float* Wv    = (const float*)d_in[5];
    const float* bv    = (const float*)d_in[6];
    const float* Wo    = (const float*)d_in[7];
    const float* bo    = (const float*)d_in[8];
    const float* ln1w  = (const float*)d_in[9];
    const float* ln1b  = (const float*)d_in[10];
    const float* W1    = (const float*)d_in[11];
    const float* b1    = (const float*)d_in[12];
    const float* W2    = (const float*)d_in[13];
    const float* b2    = (const float*)d_in[14];
    const float* ln2w  = (const float*)d_in[15];
    const float* ln2b  = (const float*)d_in[16];
    float* out = (float*)d_out;

    float *py1, *px, *py2;
    __half *psrc16, *pq16, *pk16, *pvT16, *pctx16, *px16, *ph16;
    __half *pwqT, *pwkT, *pwvT, *pwoT, *pw1T, *pw2T;
    cudaGetSymbolAddress((void**)&py1,   g_y1);
    cudaGetSymbolAddress((void**)&px,    g_x);
    cudaGetSymbolAddress((void**)&py2,   g_y2);
    cudaGetSymbolAddress((void**)&psrc16, g_src16);
    cudaGetSymbolAddress((void**)&pq16,   g_q16);
    cudaGetSymbolAddress((void**)&pk16,   g_k16);
    cudaGetSymbolAddress((void**)&pvT16,  g_vT16);
    cudaGetSymbolAddress((void**)&pctx16, g_ctx16);
    cudaGetSymbolAddress((void**)&px16,   g_x16);
    cudaGetSymbolAddress((void**)&ph16,   g_h16);
    cudaGetSymbolAddress((void**)&pwqT,   g_wqT);
    cudaGetSymbolAddress((void**)&pwkT,   g_wkT);
    cudaGetSymbolAddress((void**)&pwvT,   g_wvT);
    cudaGetSymbolAddress((void**)&pwoT,   g_woT);
    cudaGetSymbolAddress((void**)&pw1T,   g_w1T);
    cudaGetSymbolAddress((void**)&pw2T,   g_w2T);

    const int ATTN_SMEM = (128 * KROW + 4 * 64 * KROW) * sizeof(uint32_t);  // 55296 B
    cudaFuncSetAttribute(fattn_k, cudaFuncAttributeMaxDynamicSharedMemorySize, ATTN_SMEM);

    dim3 thr(256);

    // ---- weight transpose+convert (fp32 -> fp16 [N][K]) ----
    tconv_k<<<dim3(2, 32, 16), thr>>>(Wq, pwqT, DDm, DHH);
    tconv_k<<<dim3(2, 32, 16), thr>>>(Wk, pwkT, DDm, DHH);
    tconv_k<<<dim3(2, 32, 16), thr>>>(Wv, pwvT, DDm, DHH);
    tconv_k<<<dim3(32, 32, 1), thr>>>(Wo, pwoT, DDm, DDm);
    tconv_k<<<dim3(128, 32, 1), thr>>>(W1, pw1T, DDm, FFd);
    tconv_k<<<dim3(32, 128, 1), thr>>>(W2, pw2T, FFd, DDm);

    // ---- src -> fp16 ----
    conv16_k<<<(BSr * DDm / 4 + 255) / 256, thr>>>((const float4*)src, (__half2*)psrc16, BSr * DDm / 4);

    // ---- QKV projections (fp16 out; V transposed) ----
    dim3 gD(DDm / 128, BSr / 128);
    dim3 gF(FFd / 128, BSr / 128);
    hgemm_k<0, 0, 0, 1, 0><<<gD, thr>>>(psrc16, pwqT, bq, nullptr, nullptr, pq16, BSr, DDm, DDm);
    hgemm_k<0, 0, 0, 1, 0><<<gD, thr>>>(psrc16, pwkT, bk, nullptr, nullptr, pk16, BSr, DDm, DDm);
    hgemm_k<0, 0, 0, 0, 1><<<gD, thr>>>(psrc16, pwvT, bv, nullptr, nullptr, pvT16, BSr, DDm, DDm);

    // ---- flash attention (fp16 tensor cores) ----
    dim3 gAttn(SSQ / 128, HHn, BB);
    fattn_k<<<gAttn, thr, ATTN_SMEM>>>(pq16, pk16, pvT16, pctx16);

    // ---- output projection + residual, LN1 ----
    hgemm_k<0, 1, 1, 0, 0><<<gD, thr>>>(pctx16, pwoT, bo, src, py1, nullptr, BSr, DDm, DDm);
    ln_k<1><<<BSr, thr>>>(py1, ln1w, ln1b, px, px16);

    // ---- FFN ----
    hgemm_k<1, 0, 0, 1, 0><<<gF, thr>>>(px16, pw1T, b1, nullptr, nullptr, ph16, BSr, FFd, DDm);
    hgemm_k<0, 1, 1, 0, 0><<<gD, thr>>>(ph16, pw2T, b2, px, py2, nullptr, BSr, DDm, FFd);
    ln_k<0><<<BSr, thr>>>(py2, ln2w, ln2b, out, nullptr);
}